// round 6
// baseline (speedup 1.0000x reference)
#include <cuda_runtime.h>
#include <math.h>
#include <stdint.h>

// ---------------- problem constants ----------------
#define BSZ    2
#define LEN    2048
#define DIM    768
#define HDIM   1536
#define DSTATE 16
#define ROWS   (BSZ*LEN)   // 4096

#define OUT0_OFF 0
#define OUT1_OFF ((size_t)ROWS*DIM)
#define OUT2_OFF (OUT1_OFF + (size_t)ROWS*HDIM*DSTATE)

// ---------------- scratch ----------------
__device__ float g_apre[ROWS * HDIM];
__device__ float g_g   [ROWS * HDIM];
__device__ float g_a   [ROWS * HDIM];
__device__ float g_aat [ROWS * HDIM];   // k-permuted tf32 a
__device__ float g_agt [ROWS * HDIM];   // k-permuted tf32 a*g
__device__ float g_dl  [ROWS * HDIM];
__device__ float g_bm  [ROWS * DSTATE];
__device__ float g_xt  [ROWS * DIM];    // k-permuted tf32 x
__device__ float g_w1t [HDIM * DIM];    // transposed+permuted weights [N][K]
__device__ float g_w2t [HDIM * DIM];
__device__ float g_wdt [HDIM * HDIM];
__device__ float g_wft [DIM * HDIM];

// ---------------- PTX helpers ----------------
__device__ __forceinline__ uint32_t smem_u32(const void* p) {
    uint32_t a;
    asm("{ .reg .u64 t; cvta.to.shared.u64 t, %1; cvt.u32.u64 %0, t; }"
        : "=r"(a) : "l"(p));
    return a;
}
#define CP_ASYNC16(dst, src) \
    asm volatile("cp.async.cg.shared.global [%0], [%1], 16;" :: "r"(dst), "l"(src) : "memory")
#define CP_COMMIT()  asm volatile("cp.async.commit_group;" ::: "memory")
#define CP_WAIT2()   asm volatile("cp.async.wait_group 2;" ::: "memory")

__device__ __forceinline__ float rnd_tf32(float f) {
    uint32_t u;
    asm("cvt.rna.tf32.f32 %0, %1;" : "=r"(u) : "f"(f));
    return __uint_as_float(u);
}
__device__ __forceinline__ void mma_tf32(float* c, const uint32_t* a, const uint32_t* b) {
    asm volatile(
        "mma.sync.aligned.m16n8k8.row.col.f32.tf32.tf32.f32 "
        "{%0,%1,%2,%3}, {%4,%5,%6,%7}, {%8,%9}, {%0,%1,%2,%3};"
        : "+f"(c[0]), "+f"(c[1]), "+f"(c[2]), "+f"(c[3])
        : "r"(a[0]), "r"(a[1]), "r"(a[2]), "r"(a[3]), "r"(b[0]), "r"(b[1]));
}

// within-8 k permutation: pairs (k, k+4) become adjacent
__device__ __forceinline__ int perm8(int k) { return ((k & 3) << 1) | ((k >> 2) & 1); }

// ---------------- weight transpose + permute + tf32 round ------------------
// out[n][ (k&~7)|perm8(k&7) ] = rnd(in[k][n])
__global__ void __launch_bounds__(256) transpose_w_kernel(
    const float* __restrict__ w1, const float* __restrict__ w2,
    const float* __restrict__ wd, const float* __restrict__ wf,
    float* __restrict__ o1, float* __restrict__ o2,
    float* __restrict__ od, float* __restrict__ of)
{
    __shared__ float tile[32][33];
    const int z = blockIdx.z;
    const float* src; float* dst; int K, N;
    if      (z == 0) { src = w1; dst = o1; K = DIM;  N = HDIM; }
    else if (z == 1) { src = w2; dst = o2; K = DIM;  N = HDIM; }
    else if (z == 2) { src = wd; dst = od; K = HDIM; N = HDIM; }
    else             { src = wf; dst = of; K = HDIM; N = DIM;  }
    const int kb = blockIdx.y * 32, nb = blockIdx.x * 32;
    if (kb >= K || nb >= N) return;
    const int tx = threadIdx.x & 31, ty = threadIdx.x >> 5;  // 32 x 8
    #pragma unroll
    for (int i = 0; i < 4; i++)
        tile[ty + 8 * i][tx] = rnd_tf32(src[(size_t)(kb + ty + 8 * i) * N + nb + tx]);
    __syncthreads();
    const int kcol = (tx & ~7) | perm8(tx & 7);
    #pragma unroll
    for (int i = 0; i < 4; i++) {
        int n = nb + ty + 8 * i;
        dst[(size_t)n * K + kb + kcol] = tile[tx][ty + 8 * i];
    }
}

// ---------------- x: tf32 round + k-permute ----------------
__global__ void __launch_bounds__(256) permx_kernel(
    const float* __restrict__ x, float* __restrict__ xt)
{
    const int j = blockIdx.x * 256 + threadIdx.x;   // ROWS*DIM exact
    const int q = j & 7;
    const int src = (j & ~7) | ((q >> 1) + ((q & 1) << 2));
    xt[j] = rnd_tf32(x[src]);
}

// ---------------- TF32 GEMM body ----------------
// A' [M][K] k-permuted, B' [N][K] transposed+k-permuted.
// smem: per stage A 128x(36 floats, rotated chunks) + B 128x36. LDS.64 frags.
#define BK 32
#define ROWF 36                                   // floats per smem row
#define A_FLOATS (128 * ROWF)                     // 4608
#define STAGE_FLOATS (2 * A_FLOATS)               // 9216
#define GEMM_SMEM_BYTES (3 * STAGE_FLOATS * 4)    // 110592

__device__ __forceinline__ void gemm_body(
    const float* __restrict__ A, const float* __restrict__ B,
    const float* __restrict__ bias, const float* __restrict__ bias2,
    float* __restrict__ C, int N, int K, int mode,
    float* smem, int bm, int bn)
{
    const uint32_t smem_b = smem_u32(smem);
    const int tid = threadIdx.x;
    const int wid = tid >> 5, lane = tid & 31;
    const int wm = wid >> 1, wn = wid & 1;        // 2x2 warps, 64x64 tiles
    const int g = lane >> 2, t = lane & 3;

    auto load_tile = [&](int t0, int s) {
        const int k0 = t0 * BK;
        const uint32_t abase = smem_b + (uint32_t)s * (STAGE_FLOATS * 4);
        const uint32_t bbase = abase + A_FLOATS * 4;
        #pragma unroll
        for (int i = 0; i < 8; i++) {
            int idx = i * 128 + tid;
            int r = idx >> 3, c4 = idx & 7;
            uint32_t off = (uint32_t)r * (ROWF * 4) + ((uint32_t)((c4 + 2 * (r & 3)) & 7) << 4);
            CP_ASYNC16(abase + off, A + (size_t)(bm + r) * K + k0 + c4 * 4);
        }
        #pragma unroll
        for (int i = 0; i < 8; i++) {
            int idx = i * 128 + tid;
            int n = idx >> 3, c4 = idx & 7;
            uint32_t off = (uint32_t)n * (ROWF * 4) + ((uint32_t)((c4 + 2 * (n & 3)) & 7) << 4);
            CP_ASYNC16(bbase + off, B + (size_t)(bn + n) * K + k0 + c4 * 4);
        }
    };

    float acc[4][8][4];
    #pragma unroll
    for (int mi = 0; mi < 4; mi++)
        #pragma unroll
        for (int nj = 0; nj < 8; nj++)
            #pragma unroll
            for (int q = 0; q < 4; q++) acc[mi][nj][q] = 0.f;

    const int T = K / BK;
    load_tile(0, 0); CP_COMMIT();
    load_tile(1, 1); CP_COMMIT();

    const int rot = 4 * (g & 3);   // chunk rotation for this thread's rows
    int s_cur = 0, s_nxt = 2;
    for (int tt = 0; tt < T; tt++) {
        if (tt + 2 < T) load_tile(tt + 2, s_nxt);
        CP_COMMIT();
        CP_WAIT2();
        __syncthreads();

        const float* As = smem + s_cur * STAGE_FLOATS;
        const float* Bs = As + A_FLOATS;

        #pragma unroll
        for (int kk = 0; kk < 4; kk++) {
            const int chunk = ((kk * 4 + t) + rot) & 15;   // 8B-chunk position
            uint32_t af[4][4];
            #pragma unroll
            for (int mi = 0; mi < 4; mi++) {
                const int r0 = wm * 64 + mi * 16 + g;
                float2 v0 = *(const float2*)(As + r0 * ROWF + chunk * 2);
                float2 v1 = *(const float2*)(As + (r0 + 8) * ROWF + chunk * 2);
                af[mi][0] = __float_as_uint(v0.x);
                af[mi][1] = __float_as_uint(v1.x);
                af[mi][2] = __float_as_uint(v0.y);
                af[mi][3] = __float_as_uint(v1.y);
            }
            uint32_t bf[8][2];
            #pragma unroll
            for (int nj = 0; nj < 8; nj++) {
                const int n = wn * 64 + nj * 8 + g;
                float2 v = *(const float2*)(Bs + n * ROWF + chunk * 2);
                bf[nj][0] = __float_as_uint(v.x);
                bf[nj][1] = __float_as_uint(v.y);
            }
            #pragma unroll
            for (int mi = 0; mi < 4; mi++)
                #pragma unroll
                for (int nj = 0; nj < 8; nj++)
                    mma_tf32(acc[mi][nj], af[mi], bf[nj]);
        }
        __syncthreads();
        s_cur = (s_cur == 2) ? 0 : s_cur + 1;
        s_nxt = (s_nxt == 2) ? 0 : s_nxt + 1;
    }

    // epilogue
    #pragma unroll
    for (int nj = 0; nj < 8; nj++) {
        const int col = bn + wn * 64 + nj * 8 + t * 2;
        const float bz0 = __ldg(bias + col), bz1 = __ldg(bias + col + 1);
        const float e0 = (mode == 2) ? __ldg(bias2 + col) : 0.f;
        const float e1 = (mode == 2) ? __ldg(bias2 + col + 1) : 0.f;
        #pragma unroll
        for (int mi = 0; mi < 4; mi++) {
            const int row0 = bm + wm * 64 + mi * 16 + g;
            float v[4];
            v[0] = acc[mi][nj][0] + bz0 + e0;
            v[1] = acc[mi][nj][1] + bz1 + e1;
            v[2] = acc[mi][nj][2] + bz0 + e0;
            v[3] = acc[mi][nj][3] + bz1 + e1;
            #pragma unroll
            for (int q = 0; q < 4; q++) {
                if (mode == 1) v[q] = v[q] / (1.f + expf(-v[q]));
                if (mode == 2) v[q] = fmaxf(v[q], 0.f) + log1pf(expf(-fabsf(v[q])));
            }
            *(float2*)(C + (size_t)row0 * N + col)       = make_float2(v[0], v[1]);
            *(float2*)(C + (size_t)(row0 + 8) * N + col) = make_float2(v[2], v[3]);
        }
    }
}

__global__ void __launch_bounds__(128, 2) tc_gemm_single(
    const float* __restrict__ A, const float* __restrict__ B,
    const float* __restrict__ bias, const float* __restrict__ bias2,
    float* __restrict__ C, int N, int K, int mode)
{
    extern __shared__ float smem[];
    gemm_body(A, B, bias, bias2, C, N, K, mode, smem,
              blockIdx.y * 128, blockIdx.x * 128);
}

__global__ void __launch_bounds__(128, 2) tc_gemm_dual(
    const float* __restrict__ A,
    const float* __restrict__ B1, const float* __restrict__ bias1, float* __restrict__ C1,
    const float* __restrict__ B2, const float* __restrict__ bias2, float* __restrict__ C2,
    int N, int K)
{
    extern __shared__ float smem[];
    if (blockIdx.z == 0)
        gemm_body(A, B1, bias1, nullptr, C1, N, K, 0, smem,
                  blockIdx.y * 128, blockIdx.x * 128);
    else
        gemm_body(A, B2, bias2, nullptr, C2, N, K, 1, smem,
                  blockIdx.y * 128, blockIdx.x * 128);
}

// ---------------- conv(K=4)+silu; outputs a, perm(tf32 a), perm(tf32 a*g), slice
__global__ void __launch_bounds__(256) conv_fuse_kernel(
    const float* __restrict__ apre, const float* __restrict__ cw,
    const float* __restrict__ cb, const float* __restrict__ g,
    float* __restrict__ aa, float* __restrict__ aat,
    float* __restrict__ agt, float* __restrict__ out2)
{
    const int idx = blockIdx.x * 256 + threadIdx.x;
    const int d = idx % HDIM;
    const int r = idx / HDIM;
    const int l = r & (LEN - 1);
    float s = cb[d];
    #pragma unroll
    for (int j = 0; j < 4; j++) {
        const int ll = l - 3 + j;
        if (ll >= 0)
            s = fmaf(apre[(size_t)(r - 3 + j) * HDIM + d], cw[d * 4 + j], s);
    }
    const float a = s / (1.f + expf(-s));
    aa[idx] = a;
    const int dp = (d & ~7) | perm8(d & 7);
    const size_t pidx = (size_t)r * HDIM + dp;
    aat[pidx] = rnd_tf32(a);
    agt[pidx] = rnd_tf32(a * g[idx]);
    if (d >= 1) out2[(size_t)r * (HDIM - 1) + d - 1] = a;
}

// ---------------- Bm = a @ WB + bB ----------------
__global__ void __launch_bounds__(256) wb_kernel(
    const float* __restrict__ a, const float* __restrict__ WB,
    const float* __restrict__ bB, float* __restrict__ Bm)
{
    const int wid = threadIdx.x >> 5, lane = threadIdx.x & 31;
    const int r = blockIdx.x * 8 + wid;
    const float* ar = a + (size_t)r * HDIM;
    float acc[16];
    #pragma unroll
    for (int s = 0; s < 16; s++) acc[s] = 0.f;
    for (int k = lane; k < HDIM; k += 32) {
        const float av = ar[k];
        const float4* w = (const float4*)(WB + (size_t)k * 16);
        float4 w0 = w[0], w1 = w[1], w2 = w[2], w3 = w[3];
        acc[0]  = fmaf(av, w0.x, acc[0]);  acc[1]  = fmaf(av, w0.y, acc[1]);
        acc[2]  = fmaf(av, w0.z, acc[2]);  acc[3]  = fmaf(av, w0.w, acc[3]);
        acc[4]  = fmaf(av, w1.x, acc[4]);  acc[5]  = fmaf(av, w1.y, acc[5]);
        acc[6]  = fmaf(av, w1.z, acc[6]);  acc[7]  = fmaf(av, w1.w, acc[7]);
        acc[8]  = fmaf(av, w2.x, acc[8]);  acc[9]  = fmaf(av, w2.y, acc[9]);
        acc[10] = fmaf(av, w2.z, acc[10]); acc[11] = fmaf(av, w2.w, acc[11]);
        acc[12] = fmaf(av, w3.x, acc[12]); acc[13] = fmaf(av, w3.y, acc[13]);
        acc[14] = fmaf(av, w3.z, acc[14]); acc[15] = fmaf(av, w3.w, acc[15]);
    }
    #pragma unroll
    for (int off = 16; off >= 1; off >>= 1)
        #pragma unroll
        for (int s = 0; s < 16; s++)
            acc[s] += __shfl_xor_sync(0xFFFFFFFF, acc[s], off);
    if (lane < 16) Bm[r * 16 + lane] = acc[lane] + bB[lane];
}

// ---------------- fused selective scan -> hid ----------------
__global__ void __launch_bounds__(256) scan_kernel(
    const float* __restrict__ delta, const float* __restrict__ a,
    const float* __restrict__ Bm, const float* __restrict__ A,
    float* __restrict__ hid)
{
    const int g = blockIdx.x * 16 + (threadIdx.x >> 4);
    const int s = threadIdx.x & 15;
    const int b = g / HDIM;
    const int d = g % HDIM;

    const float Ae = expf(-A[d * DSTATE + s]);
    float h = 0.f;

    const float* dptr = delta + (size_t)b * LEN * HDIM + d;
    const float* aptr = a     + (size_t)b * LEN * HDIM + d;
    const float* bptr = Bm    + (size_t)b * LEN * DSTATE + s;
    float* hptr = hid + ((size_t)b * LEN * HDIM + d) * DSTATE + s;

    for (int l0 = 0; l0 < LEN; l0 += 8) {
        float dv[8], av[8], bv[8];
        #pragma unroll
        for (int u = 0; u < 8; u++) {
            dv[u] = dptr[(size_t)(l0 + u) * HDIM];
            av[u] = aptr[(size_t)(l0 + u) * HDIM];
            bv[u] = bptr[(size_t)(l0 + u) * DSTATE];
        }
        #pragma unroll
        for (int u = 0; u < 8; u++) {
            h = fmaf(Ae * dv[u], h, bv[u] * dv[u] * av[u]);
            __stcs(hptr + (size_t)(l0 + u) * (HDIM * DSTATE), h);
        }
    }
}

// ---------------------------------------------------------------------------
extern "C" void kernel_launch(void* const* d_in, const int* in_sizes, int n_in,
                              void* d_out, int out_size)
{
    const float* x  = (const float*)d_in[0];
    const float* W1 = (const float*)d_in[1];
    const float* b1 = (const float*)d_in[2];
    const float* W2 = (const float*)d_in[3];
    const float* b2 = (const float*)d_in[4];
    const float* cw = (const float*)d_in[5];
    const float* cb = (const float*)d_in[6];
    const float* Wf = (const float*)d_in[7];
    const float* bf = (const float*)d_in[8];
    const float* A  = (const float*)d_in[9];
    const float* WB = (const float*)d_in[10];
    const float* bB = (const float*)d_in[11];
    const float* WD = (const float*)d_in[14];
    const float* bD = (const float*)d_in[15];
    const float* Dv = (const float*)d_in[16];

    float* out = (float*)d_out;

    float *apre, *gg, *aa, *aat, *agt, *dl, *bm;
    float *xt, *w1t, *w2t, *wdt, *wft;
    cudaGetSymbolAddress((void**)&apre, g_apre);
    cudaGetSymbolAddress((void**)&gg,   g_g);
    cudaGetSymbolAddress((void**)&aa,   g_a);
    cudaGetSymbolAddress((void**)&aat,  g_aat);
    cudaGetSymbolAddress((void**)&agt,  g_agt);
    cudaGetSymbolAddress((void**)&dl,   g_dl);
    cudaGetSymbolAddress((void**)&bm,   g_bm);
    cudaGetSymbolAddress((void**)&xt,   g_xt);
    cudaGetSymbolAddress((void**)&w1t,  g_w1t);
    cudaGetSymbolAddress((void**)&w2t,  g_w2t);
    cudaGetSymbolAddress((void**)&wdt,  g_wdt);
    cudaGetSymbolAddress((void**)&wft,  g_wft);

    cudaFuncSetAttribute(tc_gemm_single, cudaFuncAttributeMaxDynamicSharedMemorySize, GEMM_SMEM_BYTES);
    cudaFuncSetAttribute(tc_gemm_dual,   cudaFuncAttributeMaxDynamicSharedMemorySize, GEMM_SMEM_BYTES);

    // 0) weight transpose+permute+round; x permute+round
    transpose_w_kernel<<<dim3(HDIM/32, HDIM/32, 4), 256>>>(
        W1, W2, WD, Wf, w1t, w2t, wdt, wft);
    permx_kernel<<<(ROWS*DIM)/256, 256>>>(x, xt);

    // 1+2) apre = x@W1+b1 ; g = silu(x@W2+b2)
    tc_gemm_dual<<<dim3(HDIM/128, ROWS/128, 2), 128, GEMM_SMEM_BYTES>>>(
        xt, w1t, b1, apre, w2t, b2, gg, HDIM, DIM);
    // 3) conv + silu + a*g + slice
    conv_fuse_kernel<<<(ROWS*HDIM)/256, 256>>>(apre, cw, cb, gg, aa, aat, agt, out + OUT2_OFF);
    // 4) delta = softplus(Dvec + a@WD + bD)
    tc_gemm_single<<<dim3(HDIM/128, ROWS/128), 128, GEMM_SMEM_BYTES>>>(
        aat, wdt, bD, Dv, dl, HDIM, HDIM, 2);
    // 5) Bm = a@WB + bB
    wb_kernel<<<ROWS/8, 256>>>(aa, WB, bB, bm);
    // 6) output = (a*g)@Wf + bf
    tc_gemm_single<<<dim3(DIM/128, ROWS/128), 128, GEMM_SMEM_BYTES>>>(
        agt, wft, bf, nullptr, out + OUT0_OFF, DIM, HDIM, 0);
    // 7) hid via fused selective scan
    scan_kernel<<<(BSZ*HDIM)/16, 256>>>(dl, aa, bm, A, out + OUT1_OFF);
}

// round 8
// speedup vs baseline: 1.1957x; 1.1957x over previous
#include <cuda_runtime.h>
#include <math.h>
#include <stdint.h>

// ---------------- problem constants ----------------
#define BSZ    2
#define LEN    2048
#define DIM    768
#define HDIM   1536
#define DSTATE 16
#define ROWS   (BSZ*LEN)   // 4096

#define OUT0_OFF 0
#define OUT1_OFF ((size_t)ROWS*DIM)
#define OUT2_OFF (OUT1_OFF + (size_t)ROWS*HDIM*DSTATE)

// ---------------- scratch ----------------
__device__ float g_apre[ROWS * HDIM];
__device__ float g_g   [ROWS * HDIM];
__device__ float g_a   [ROWS * HDIM];
__device__ float g_aat [ROWS * HDIM];
__device__ float g_agt [ROWS * HDIM];
__device__ float g_dl  [ROWS * HDIM];
__device__ float g_bm  [ROWS * DSTATE];
__device__ float g_xt  [ROWS * DIM];
__device__ float g_w1t [DIM * HDIM];
__device__ float g_w2t [DIM * HDIM];
__device__ float g_wdt [HDIM * HDIM];
__device__ float g_wft [HDIM * DIM];

// ---------------- PTX helpers ----------------
__device__ __forceinline__ uint32_t smem_u32(const void* p) {
    uint32_t a;
    asm("{ .reg .u64 t; cvta.to.shared.u64 t, %1; cvt.u32.u64 %0, t; }"
        : "=r"(a) : "l"(p));
    return a;
}
#define CP_ASYNC16(dst, src) \
    asm volatile("cp.async.cg.shared.global [%0], [%1], 16;" :: "r"(dst), "l"(src) : "memory")
#define CP_COMMIT()  asm volatile("cp.async.commit_group;" ::: "memory")
#define CP_WAIT2()   asm volatile("cp.async.wait_group 2;" ::: "memory")

__device__ __forceinline__ float rnd_tf32(float f) {
    uint32_t u;
    asm("cvt.rna.tf32.f32 %0, %1;" : "=r"(u) : "f"(f));
    return __uint_as_float(u);
}
__device__ __forceinline__ void mma_tf32(float* c, const uint32_t* a, const uint32_t* b) {
    asm volatile(
        "mma.sync.aligned.m16n8k8.row.col.f32.tf32.tf32.f32 "
        "{%0,%1,%2,%3}, {%4,%5,%6,%7}, {%8,%9}, {%0,%1,%2,%3};"
        : "+f"(c[0]), "+f"(c[1]), "+f"(c[2]), "+f"(c[3])
        : "r"(a[0]), "r"(a[1]), "r"(a[2]), "r"(a[3]), "r"(b[0]), "r"(b[1]));
}

// ---------------- pre-round x + all weights to tf32 ----------------
#define XT4  (ROWS*DIM/4)
#define W14  (DIM*HDIM/4)
#define WD4  (HDIM*HDIM/4)
#define RB0  XT4
#define RB1  (RB0 + W14)
#define RB2  (RB1 + W14)
#define RB3  (RB2 + WD4)
#define RTOT (RB3 + W14)

__global__ void __launch_bounds__(256) round_all_kernel(
    const float4* __restrict__ x,  const float4* __restrict__ w1,
    const float4* __restrict__ w2, const float4* __restrict__ wd,
    const float4* __restrict__ wf,
    float4* __restrict__ xt,  float4* __restrict__ w1t,
    float4* __restrict__ w2t, float4* __restrict__ wdt,
    float4* __restrict__ wft)
{
    int i = blockIdx.x * 256 + threadIdx.x;
    if (i >= RTOT) return;
    const float4* s; float4* d; int off;
    if      (i < RB0) { s = x;  d = xt;  off = i; }
    else if (i < RB1) { s = w1; d = w1t; off = i - RB0; }
    else if (i < RB2) { s = w2; d = w2t; off = i - RB1; }
    else if (i < RB3) { s = wd; d = wdt; off = i - RB2; }
    else              { s = wf; d = wft; off = i - RB3; }
    float4 v = s[off];
    v.x = rnd_tf32(v.x); v.y = rnd_tf32(v.y);
    v.z = rnd_tf32(v.z); v.w = rnd_tf32(v.w);
    d[off] = v;
}

// ---------------- TF32 tensor-core GEMM body (R5 layout) --------------------
// 128x128 CTA tile, 4 warps (64x64 each), 3-stage cp.async pipeline.
#define BK 32
#define ASTRIDE 36
#define BSTRIDE 136
#define A_FLOATS (128 * ASTRIDE)                 // 4608
#define STAGE_FLOATS (A_FLOATS + BK * BSTRIDE)   // 8960
#define GEMM_SMEM_BYTES (3 * STAGE_FLOATS * 4)   // 107520

__device__ __forceinline__ void gemm_body(
    const float* __restrict__ A, const float* __restrict__ B,
    const float* __restrict__ bias, const float* __restrict__ bias2,
    float* __restrict__ C, int N, int K, int mode,
    float* smem, int bm, int bn)
{
    const uint32_t smem_b = smem_u32(smem);
    const int tid = threadIdx.x;
    const int wid = tid >> 5, lane = tid & 31;
    const int wm = wid >> 1, wn = wid & 1;      // 2x2 warp grid, 64x64 warp tile
    const int g = lane >> 2, t = lane & 3;

    auto load_tile = [&](int t0, int s) {
        const int k0 = t0 * BK;
        const uint32_t abase = smem_b + (uint32_t)s * (STAGE_FLOATS * 4);
        const uint32_t bbase = abase + A_FLOATS * 4;
        #pragma unroll
        for (int i = 0; i < 8; i++) {
            int idx = i * 128 + tid;
            int r = idx >> 3, c4 = idx & 7;
            CP_ASYNC16(abase + (uint32_t)(r * ASTRIDE + c4 * 4) * 4,
                       A + (size_t)(bm + r) * K + k0 + c4 * 4);
        }
        #pragma unroll
        for (int i = 0; i < 8; i++) {
            int idx = i * 128 + tid;
            int kk = idx >> 5, c4 = idx & 31;
            CP_ASYNC16(bbase + (uint32_t)(kk * BSTRIDE + c4 * 4) * 4,
                       B + (size_t)(k0 + kk) * N + bn + c4 * 4);
        }
    };

    float acc[4][8][4];
    #pragma unroll
    for (int mi = 0; mi < 4; mi++)
        #pragma unroll
        for (int nj = 0; nj < 8; nj++)
            #pragma unroll
            for (int q = 0; q < 4; q++) acc[mi][nj][q] = 0.f;

    const int T = K / BK;
    load_tile(0, 0); CP_COMMIT();
    load_tile(1, 1); CP_COMMIT();

    int s_cur = 0, s_nxt = 2;
    for (int tt = 0; tt < T; tt++) {
        if (tt + 2 < T) load_tile(tt + 2, s_nxt);
        CP_COMMIT();
        CP_WAIT2();
        __syncthreads();

        const float* As = smem + s_cur * STAGE_FLOATS;
        const float* Bs = As + A_FLOATS;

        #pragma unroll
        for (int kk = 0; kk < 4; kk++) {
            uint32_t af[4][4];
            #pragma unroll
            for (int mi = 0; mi < 4; mi++) {
                const float* ap = As + (wm * 64 + mi * 16 + g) * ASTRIDE + kk * 8 + t;
                af[mi][0] = __float_as_uint(ap[0]);
                af[mi][1] = __float_as_uint(ap[8 * ASTRIDE]);
                af[mi][2] = __float_as_uint(ap[4]);
                af[mi][3] = __float_as_uint(ap[8 * ASTRIDE + 4]);
            }
            uint32_t bf[8][2];
            #pragma unroll
            for (int nj = 0; nj < 8; nj++) {
                const float* bp = Bs + (kk * 8 + t) * BSTRIDE + wn * 64 + nj * 8 + g;
                bf[nj][0] = __float_as_uint(bp[0]);
                bf[nj][1] = __float_as_uint(bp[4 * BSTRIDE]);
            }
            #pragma unroll
            for (int mi = 0; mi < 4; mi++)
                #pragma unroll
                for (int nj = 0; nj < 8; nj++)
                    mma_tf32(acc[mi][nj], af[mi], bf[nj]);
        }
        __syncthreads();
        s_cur = (s_cur == 2) ? 0 : s_cur + 1;
        s_nxt = (s_nxt == 2) ? 0 : s_nxt + 1;
    }

    // epilogue
    #pragma unroll
    for (int nj = 0; nj < 8; nj++) {
        const int col = bn + wn * 64 + nj * 8 + t * 2;
        const float bz0 = __ldg(bias + col), bz1 = __ldg(bias + col + 1);
        const float e0 = (mode == 2) ? __ldg(bias2 + col) : 0.f;
        const float e1 = (mode == 2) ? __ldg(bias2 + col + 1) : 0.f;
        #pragma unroll
        for (int mi = 0; mi < 4; mi++) {
            const int row0 = bm + wm * 64 + mi * 16 + g;
            float v[4];
            v[0] = acc[mi][nj][0] + bz0 + e0;
            v[1] = acc[mi][nj][1] + bz1 + e1;
            v[2] = acc[mi][nj][2] + bz0 + e0;
            v[3] = acc[mi][nj][3] + bz1 + e1;
            #pragma unroll
            for (int q = 0; q < 4; q++) {
                if (mode == 1) v[q] = v[q] / (1.f + expf(-v[q]));
                if (mode == 2) v[q] = fmaxf(v[q], 0.f) + log1pf(expf(-fabsf(v[q])));
            }
            *(float2*)(C + (size_t)row0 * N + col)       = make_float2(v[0], v[1]);
            *(float2*)(C + (size_t)(row0 + 8) * N + col) = make_float2(v[2], v[3]);
        }
    }
}

// dual launch: z=0 -> C1 = A@B1 + bias1 (mode m1); z=1 -> C2 = A2@B2 + bias2 (mode m2)
// grid.x sized for N1/128; z=1 blocks with x >= N2/128 exit.
__global__ void __launch_bounds__(128, 2) tc_gemm_dual(
    const float* __restrict__ A1, const float* __restrict__ B1,
    const float* __restrict__ bias1, const float* __restrict__ biasx1,
    float* __restrict__ C1, int N1, int m1,
    const float* __restrict__ A2, const float* __restrict__ B2,
    const float* __restrict__ bias2, const float* __restrict__ biasx2,
    float* __restrict__ C2, int N2, int m2,
    int K)
{
    extern __shared__ float smem[];
    if (blockIdx.z == 0) {
        gemm_body(A1, B1, bias1, biasx1, C1, N1, K, m1, smem,
                  blockIdx.y * 128, blockIdx.x * 128);
    } else {
        if ((int)blockIdx.x * 128 >= N2) return;
        gemm_body(A2, B2, bias2, biasx2, C2, N2, K, m2, smem,
                  blockIdx.y * 128, blockIdx.x * 128);
    }
}

// ---------------- conv(K=4)+silu; writes a, tf32(a), tf32(a*g), slice ------
__global__ void __launch_bounds__(256) conv_fuse_kernel(
    const float* __restrict__ apre, const float* __restrict__ cw,
    const float* __restrict__ cb, const float* __restrict__ g,
    float* __restrict__ aa, float* __restrict__ aat,
    float* __restrict__ agt, float* __restrict__ out2)
{
    const int idx = blockIdx.x * 256 + threadIdx.x;
    const int d = idx % HDIM;
    const int r = idx / HDIM;
    const int l = r & (LEN - 1);
    float s = cb[d];
    #pragma unroll
    for (int j = 0; j < 4; j++) {
        const int ll = l - 3 + j;
        if (ll >= 0)
            s = fmaf(apre[(size_t)(r - 3 + j) * HDIM + d], cw[d * 4 + j], s);
    }
    const float a = s / (1.f + expf(-s));
    aa[idx]  = a;
    aat[idx] = rnd_tf32(a);
    agt[idx] = rnd_tf32(a * g[idx]);
    if (d >= 1) out2[(size_t)r * (HDIM - 1) + d - 1] = a;
}

// ---------------- Bm = a @ WB + bB ----------------
__global__ void __launch_bounds__(256) wb_kernel(
    const float* __restrict__ a, const float* __restrict__ WB,
    const float* __restrict__ bB, float* __restrict__ Bm)
{
    const int wid = threadIdx.x >> 5, lane = threadIdx.x & 31;
    const int r = blockIdx.x * 8 + wid;
    const float* ar = a + (size_t)r * HDIM;
    float acc[16];
    #pragma unroll
    for (int s = 0; s < 16; s++) acc[s] = 0.f;
    for (int k = lane; k < HDIM; k += 32) {
        const float av = ar[k];
        const float4* w = (const float4*)(WB + (size_t)k * 16);
        float4 w0 = w[0], w1 = w[1], w2 = w[2], w3 = w[3];
        acc[0]  = fmaf(av, w0.x, acc[0]);  acc[1]  = fmaf(av, w0.y, acc[1]);
        acc[2]  = fmaf(av, w0.z, acc[2]);  acc[3]  = fmaf(av, w0.w, acc[3]);
        acc[4]  = fmaf(av, w1.x, acc[4]);  acc[5]  = fmaf(av, w1.y, acc[5]);
        acc[6]  = fmaf(av, w1.z, acc[6]);  acc[7]  = fmaf(av, w1.w, acc[7]);
        acc[8]  = fmaf(av, w2.x, acc[8]);  acc[9]  = fmaf(av, w2.y, acc[9]);
        acc[10] = fmaf(av, w2.z, acc[10]); acc[11] = fmaf(av, w2.w, acc[11]);
        acc[12] = fmaf(av, w3.x, acc[12]); acc[13] = fmaf(av, w3.y, acc[13]);
        acc[14] = fmaf(av, w3.z, acc[14]); acc[15] = fmaf(av, w3.w, acc[15]);
    }
    #pragma unroll
    for (int off = 16; off >= 1; off >>= 1)
        #pragma unroll
        for (int s = 0; s < 16; s++)
            acc[s] += __shfl_xor_sync(0xFFFFFFFF, acc[s], off);
    if (lane < 16) Bm[r * 16 + lane] = acc[lane] + bB[lane];
}

// ---------------- fused selective scan -> hid (streaming stores) -----------
__global__ void __launch_bounds__(256) scan_kernel(
    const float* __restrict__ delta, const float* __restrict__ a,
    const float* __restrict__ Bm, const float* __restrict__ A,
    float* __restrict__ hid)
{
    const int g = blockIdx.x * 16 + (threadIdx.x >> 4);
    const int s = threadIdx.x & 15;
    const int b = g / HDIM;
    const int d = g % HDIM;

    const float Ae = expf(-A[d * DSTATE + s]);
    float h = 0.f;

    const float* dptr = delta + (size_t)b * LEN * HDIM + d;
    const float* aptr = a     + (size_t)b * LEN * HDIM + d;
    const float* bptr = Bm    + (size_t)b * LEN * DSTATE + s;
    float* hptr = hid + ((size_t)b * LEN * HDIM + d) * DSTATE + s;

    for (int l0 = 0; l0 < LEN; l0 += 8) {
        float dv[8], av[8], bv[8];
        #pragma unroll
        for (int u = 0; u < 8; u++) {
            dv[u] = dptr[(size_t)(l0 + u) * HDIM];
            av[u] = aptr[(size_t)(l0 + u) * HDIM];
            bv[u] = bptr[(size_t)(l0 + u) * DSTATE];
        }
        #pragma unroll
        for (int u = 0; u < 8; u++) {
            h = fmaf(Ae * dv[u], h, bv[u] * dv[u] * av[u]);
            __stcs(hptr + (size_t)(l0 + u) * (HDIM * DSTATE), h);
        }
    }
}

// ---------------------------------------------------------------------------
extern "C" void kernel_launch(void* const* d_in, const int* in_sizes, int n_in,
                              void* d_out, int out_size)
{
    const float* x  = (const float*)d_in[0];
    const float* W1 = (const float*)d_in[1];
    const float* b1 = (const float*)d_in[2];
    const float* W2 = (const float*)d_in[3];
    const float* b2 = (const float*)d_in[4];
    const float* cw = (const float*)d_in[5];
    const float* cb = (const float*)d_in[6];
    const float* Wf = (const float*)d_in[7];
    const float* bf = (const float*)d_in[8];
    const float* A  = (const float*)d_in[9];
    const float* WB = (const float*)d_in[10];
    const float* bB = (const float*)d_in[11];
    const float* WD = (const float*)d_in[14];
    const float* bD = (const float*)d_in[15];
    const float* Dv = (const float*)d_in[16];

    float* out = (float*)d_out;

    float *apre, *gg, *aa, *aat, *agt, *dl, *bm;
    float *xt, *w1t, *w2t, *wdt, *wft;
    cudaGetSymbolAddress((void**)&apre, g_apre);
    cudaGetSymbolAddress((void**)&gg,   g_g);
    cudaGetSymbolAddress((void**)&aa,   g_a);
    cudaGetSymbolAddress((void**)&aat,  g_aat);
    cudaGetSymbolAddress((void**)&agt,  g_agt);
    cudaGetSymbolAddress((void**)&dl,   g_dl);
    cudaGetSymbolAddress((void**)&bm,   g_bm);
    cudaGetSymbolAddress((void**)&xt,   g_xt);
    cudaGetSymbolAddress((void**)&w1t,  g_w1t);
    cudaGetSymbolAddress((void**)&w2t,  g_w2t);
    cudaGetSymbolAddress((void**)&wdt,  g_wdt);
    cudaGetSymbolAddress((void**)&wft,  g_wft);

    cudaFuncSetAttribute(tc_gemm_dual, cudaFuncAttributeMaxDynamicSharedMemorySize, GEMM_SMEM_BYTES);

    // 0) pre-round x + weights to tf32
    round_all_kernel<<<(RTOT + 255) / 256, 256>>>(
        (const float4*)x, (const float4*)W1, (const float4*)W2,
        (const float4*)WD, (const float4*)Wf,
        (float4*)xt, (float4*)w1t, (float4*)w2t, (float4*)wdt, (float4*)wft);

    // 1+2) apre = x@W1+b1 (z=0) ; g = silu(x@W2+b2) (z=1) — one co-resident launch
    tc_gemm_dual<<<dim3(HDIM/128, ROWS/128, 2), 128, GEMM_SMEM_BYTES>>>(
        xt, w1t, b1, nullptr, apre, HDIM, 0,
        xt, w2t, b2, nullptr, gg,   HDIM, 1,
        DIM);

    // 3) conv + silu + a*g + slice
    conv_fuse_kernel<<<(ROWS*HDIM)/256, 256>>>(apre, cw, cb, gg, aa, aat, agt, out + OUT2_OFF);

    // 4) Bm = a@WB + bB (small, feeds scan)
    wb_kernel<<<ROWS/8, 256>>>(aa, WB, bB, bm);

    // 5+6) delta = softplus(...) (z=0) ∥ output = (a*g)@Wf + bf (z=1), both K=HDIM
    tc_gemm_dual<<<dim3(HDIM/128, ROWS/128, 2), 128, GEMM_SMEM_BYTES>>>(
        aat, wdt, bD, Dv,      dl,              HDIM, 2,
        agt, wft, bf, nullptr, out + OUT0_OFF,  DIM,  0,
        HDIM);

    // 7) hid via fused selective scan
    scan_kernel<<<(BSZ*HDIM)/16, 256>>>(dl, aa, bm, A, out + OUT1_OFF);
}